// round 1
// baseline (speedup 1.0000x reference)
#include <cuda_runtime.h>
#include <cuda_bf16.h>

// ---------------- problem constants ----------------
#define B_ 32
#define N_ 512
#define H_ 768
#define R_ 5
#define L_ 2
#define FF_ 1536
#define LN_EPS 1e-5f

// ---------------- scratch (device globals; no allocation) ----------------
// bufA / bufB: [B,R,N,H] sized, reused for agg/msg/merged/ffn intermediates
__device__ float g_bufA[(long)B_ * R_ * N_ * H_];
__device__ float g_bufB[(long)B_ * R_ * N_ * H_];
__device__ float g_hidden[(long)B_ * N_ * H_];
__device__ float g_x[(long)B_ * N_ * H_];
__device__ float g_invdeg[B_ * R_ * N_];
__device__ float g_w[L_ * B_ * R_];

// ---------------- generic fp32 SGEMM: C[z] = A[z] @ B[idxB] (+bias)(*rowscale)(relu) ----
// BM=BN=128, BK=8, 256 threads, 8x8 per thread, double-buffered smem.
// Requires M%128==0, N%128==0, K%8==0 (true for all shapes here).
template <bool RELU, bool BIAS, bool RSCALE>
__global__ __launch_bounds__(256) void sgemm_kernel(
    const float* __restrict__ Ag, const float* __restrict__ Bg,
    float* __restrict__ Cg, int M, int Nn, int K,
    long sA, long sB, long sC,
    int bdivB, int bmodB,
    const float* __restrict__ biasg, long sBias, int bdivBias, int bmodBias,
    const float* __restrict__ rscaleg, long sR)
{
    const int z = blockIdx.z;
    const float* A = Ag + (long)z * sA;
    const float* Bp = Bg + (long)((z / bdivB) % bmodB) * sB;
    float* C = Cg + (long)z * sC;

    const int m0 = blockIdx.y * 128;
    const int n0 = blockIdx.x * 128;
    const int tid = threadIdx.x;

    __shared__ float As[2][8][128];
    __shared__ float Bs[2][8][128];

    const int aRow = tid >> 1;            // 0..127
    const int aCol = (tid & 1) * 4;       // 0 or 4
    const int bRow = tid >> 5;            // 0..7
    const int bCol = (tid & 31) * 4;      // 0..124

    const float* Aload = A + (long)(m0 + aRow) * K + aCol;
    const float* Bload = Bp + (long)bRow * Nn + (n0 + bCol);

    float acc[8][8];
#pragma unroll
    for (int i = 0; i < 8; i++)
#pragma unroll
        for (int j = 0; j < 8; j++) acc[i][j] = 0.0f;

    // prefetch tile 0
    float4 a4 = *(const float4*)(Aload);
    float4 b4 = *(const float4*)(Bload);
    As[0][aCol + 0][aRow] = a4.x;
    As[0][aCol + 1][aRow] = a4.y;
    As[0][aCol + 2][aRow] = a4.z;
    As[0][aCol + 3][aRow] = a4.w;
    *(float4*)&Bs[0][bRow][bCol] = b4;
    __syncthreads();

    const int tmRow = (tid >> 4) * 8;   // 0..120
    const int tnCol = (tid & 15) * 8;   // 0..120

    const int nk = K >> 3;
    int s = 0;
    for (int kt = 0; kt < nk; kt++) {
        if (kt + 1 < nk) {
            a4 = *(const float4*)(Aload + (long)(kt + 1) * 8);
            b4 = *(const float4*)(Bload + (long)(kt + 1) * 8 * Nn);
        }
#pragma unroll
        for (int kk = 0; kk < 8; kk++) {
            float af[8], bf[8];
            *(float4*)&af[0] = *(const float4*)&As[s][kk][tmRow];
            *(float4*)&af[4] = *(const float4*)&As[s][kk][tmRow + 4];
            *(float4*)&bf[0] = *(const float4*)&Bs[s][kk][tnCol];
            *(float4*)&bf[4] = *(const float4*)&Bs[s][kk][tnCol + 4];
#pragma unroll
            for (int i = 0; i < 8; i++)
#pragma unroll
                for (int j = 0; j < 8; j++) acc[i][j] = fmaf(af[i], bf[j], acc[i][j]);
        }
        if (kt + 1 < nk) {
            s ^= 1;
            As[s][aCol + 0][aRow] = a4.x;
            As[s][aCol + 1][aRow] = a4.y;
            As[s][aCol + 2][aRow] = a4.z;
            As[s][aCol + 3][aRow] = a4.w;
            *(float4*)&Bs[s][bRow][bCol] = b4;
            __syncthreads();
        }
    }

    // epilogue
    float bv[8];
    if (BIAS) {
        const float* bp = biasg + (long)((z / bdivBias) % bmodBias) * sBias + n0 + tnCol;
#pragma unroll
        for (int j = 0; j < 8; j++) bv[j] = bp[j];
    }
#pragma unroll
    for (int i = 0; i < 8; i++) {
        const int row = m0 + tmRow + i;
        float rs = 1.0f;
        if (RSCALE) rs = rscaleg[(long)z * sR + row];
#pragma unroll
        for (int j = 0; j < 8; j += 4) {
            float4 v;
            v.x = acc[i][j + 0];
            v.y = acc[i][j + 1];
            v.z = acc[i][j + 2];
            v.w = acc[i][j + 3];
            if (RSCALE) { v.x *= rs; v.y *= rs; v.z *= rs; v.w *= rs; }
            if (BIAS) { v.x += bv[j + 0]; v.y += bv[j + 1]; v.z += bv[j + 2]; v.w += bv[j + 3]; }
            if (RELU) {
                v.x = fmaxf(v.x, 0.0f); v.y = fmaxf(v.y, 0.0f);
                v.z = fmaxf(v.z, 0.0f); v.w = fmaxf(v.w, 0.0f);
            }
            *(float4*)&C[(long)row * Nn + n0 + tnCol + j] = v;
        }
    }
}

// ---------------- invdeg: 1/max(rowsum(adj),1), one warp per row ----------------
__global__ void invdeg_kernel(const float* __restrict__ adj, float* __restrict__ invdeg)
{
    const int row = blockIdx.x * 8 + (threadIdx.x >> 5);
    const int lane = threadIdx.x & 31;
    const float* p = adj + (long)row * N_;
    float s = 0.0f;
    for (int m = lane; m < N_; m += 32) s += p[m];
#pragma unroll
    for (int o = 16; o > 0; o >>= 1) s += __shfl_xor_sync(0xFFFFFFFFu, s, o);
    if (lane == 0) invdeg[row] = 1.0f / fmaxf(s, 1.0f);
}

// ---------------- gate: pooled mean over N, logits, softmax -> w[b,r] ----------------
__global__ void gate_kernel(const float* __restrict__ x, const float* __restrict__ gW,
                            const float* __restrict__ gb, float* __restrict__ w_out)
{
    __shared__ float pooled[H_];
    __shared__ float logits[R_];
    const int b = blockIdx.x;
    for (int h = threadIdx.x; h < H_; h += blockDim.x) {
        float s = 0.0f;
        const float* p = x + (long)b * N_ * H_ + h;
        for (int n = 0; n < N_; n++) s += p[(long)n * H_];
        pooled[h] = s * (1.0f / N_);
    }
    __syncthreads();
    if (threadIdx.x < R_) {
        float s = gb[threadIdx.x];
        for (int h = 0; h < H_; h++) s = fmaf(pooled[h], gW[h * R_ + threadIdx.x], s);
        logits[threadIdx.x] = s;
    }
    __syncthreads();
    if (threadIdx.x == 0) {
        float mx = logits[0];
        for (int r = 1; r < R_; r++) mx = fmaxf(mx, logits[r]);
        float e[R_], den = 0.0f;
        for (int r = 0; r < R_; r++) { e[r] = expf(logits[r] - mx); den += e[r]; }
        const float inv = 1.0f / den;
        for (int r = 0; r < R_; r++) w_out[b * R_ + r] = e[r] * inv;
    }
}

// ---------------- merge over relations: out[b,n,h] = sum_r w[b,r]*msg[b,r,n,h] ------
__global__ void merge_kernel(const float* __restrict__ msg, const float* __restrict__ w,
                             float* __restrict__ out)
{
    const long idx = (long)blockIdx.x * blockDim.x + threadIdx.x;
    const int b = (int)(idx / ((long)N_ * H_));
    const long nh = idx % ((long)N_ * H_);
    const float* wb = w + b * R_;
    float s = 0.0f;
#pragma unroll
    for (int r = 0; r < R_; r++)
        s = fmaf(__ldg(&wb[r]), msg[((long)(b * R_ + r)) * N_ * H_ + nh], s);
    out[idx] = s;
}

// ---------------- layernorm: out = LN(xa+xb)*g + be, one block per row ----------------
__global__ void ln_kernel(const float* __restrict__ xa, const float* __restrict__ xb,
                          const float* __restrict__ g, const float* __restrict__ be,
                          float* __restrict__ out)
{
    const int row = blockIdx.x;
    const float* pa = xa + (long)row * H_;
    const float* pb = xb + (long)row * H_;
    float v[3];
    float s = 0.0f, sq = 0.0f;
#pragma unroll
    for (int i = 0; i < 3; i++) {
        const int h = threadIdx.x + i * 256;
        const float t = pa[h] + pb[h];
        v[i] = t; s += t; sq = fmaf(t, t, sq);
    }
    const int lane = threadIdx.x & 31, wid = threadIdx.x >> 5;
#pragma unroll
    for (int o = 16; o > 0; o >>= 1) {
        s += __shfl_xor_sync(0xFFFFFFFFu, s, o);
        sq += __shfl_xor_sync(0xFFFFFFFFu, sq, o);
    }
    __shared__ float red[2][8];
    if (lane == 0) { red[0][wid] = s; red[1][wid] = sq; }
    __syncthreads();
    if (threadIdx.x == 0) {
        float S = 0.0f, Q = 0.0f;
        for (int i = 0; i < 8; i++) { S += red[0][i]; Q += red[1][i]; }
        red[0][0] = S; red[1][0] = Q;
    }
    __syncthreads();
    const float mu = red[0][0] * (1.0f / H_);
    const float var = red[1][0] * (1.0f / H_) - mu * mu;
    const float inv = rsqrtf(var + LN_EPS);
#pragma unroll
    for (int i = 0; i < 3; i++) {
        const int h = threadIdx.x + i * 256;
        out[(long)row * H_ + h] = (v[i] - mu) * inv * g[h] + be[h];
    }
}

// ---------------- relation-weight statistic (deterministic, single block) ------------
__global__ void stat_kernel(const float* __restrict__ w_all, float* __restrict__ out)
{
    if (threadIdx.x < R_) {
        float s = 0.0f;
        for (int i = 0; i < L_ * B_; i++) s += w_all[i * R_ + threadIdx.x];
        out[threadIdx.x] = s * (1.0f / (L_ * B_));
    }
}

// ---------------- launch ----------------
extern "C" void kernel_launch(void* const* d_in, const int* in_sizes, int n_in,
                              void* d_out, int out_size)
{
    const float* node  = (const float*)d_in[0];   // [B,N,H]
    const float* adj   = (const float*)d_in[1];   // [B,R,N,N]
    const float* rel_W = (const float*)d_in[2];   // [L,R,H,H]
    const float* rel_b = (const float*)d_in[3];   // [L,R,H]
    const float* gateW = (const float*)d_in[4];   // [L,H,R]
    const float* gateb = (const float*)d_in[5];   // [L,R]
    const float* outW  = (const float*)d_in[6];   // [L,H,H]
    const float* outb  = (const float*)d_in[7];   // [L,H]
    const float* ln1g  = (const float*)d_in[8];   // [L,H]
    const float* ln1b  = (const float*)d_in[9];   // [L,H]
    const float* fW1   = (const float*)d_in[10];  // [L,H,FF]
    const float* fb1   = (const float*)d_in[11];  // [L,FF]
    const float* fW2   = (const float*)d_in[12];  // [L,FF,H]
    const float* fb2   = (const float*)d_in[13];  // [L,H]
    const float* ln2g  = (const float*)d_in[14];  // [L,H]
    const float* ln2b  = (const float*)d_in[15];  // [L,H]
    float* out = (float*)d_out;                   // [B*N*H] x, then [R] stats

    float *bufA, *bufB, *hidden, *xbuf, *invdeg, *wbuf;
    cudaGetSymbolAddress((void**)&bufA, g_bufA);
    cudaGetSymbolAddress((void**)&bufB, g_bufB);
    cudaGetSymbolAddress((void**)&hidden, g_hidden);
    cudaGetSymbolAddress((void**)&xbuf, g_x);
    cudaGetSymbolAddress((void**)&invdeg, g_invdeg);
    cudaGetSymbolAddress((void**)&wbuf, g_w);

    const int BIG = 1 << 28;

    // degree normalization (layer-invariant)
    invdeg_kernel<<<(B_ * R_ * N_) / 8, 256>>>(adj, invdeg);

    for (int l = 0; l < L_; l++) {
        const float* x = (l == 0) ? node : xbuf;

        // gate weights (uses pre-update x)
        gate_kernel<<<B_, 256>>>(x, gateW + (long)l * H_ * R_, gateb + l * R_,
                                 wbuf + l * B_ * R_);

        // agg[z] = (adj[z] @ x[b]) * invdeg[z,row]   (z = b*R + r)
        {
            dim3 grid(H_ / 128, N_ / 128, B_ * R_);
            sgemm_kernel<false, false, true><<<grid, 256>>>(
                adj, x, bufA, N_, H_, N_,
                (long)N_ * N_, (long)N_ * H_, (long)N_ * H_,
                R_, BIG,
                nullptr, 0, 1, 1,
                invdeg, N_);
        }
        // msg[z] = relu(agg[z] @ rel_W[l, z%R] + rel_b[l, z%R])
        {
            dim3 grid(H_ / 128, N_ / 128, B_ * R_);
            sgemm_kernel<true, true, false><<<grid, 256>>>(
                bufA, rel_W + (long)l * R_ * H_ * H_, bufB, N_, H_, H_,
                (long)N_ * H_, (long)H_ * H_, (long)N_ * H_,
                1, R_,
                rel_b + (long)l * R_ * H_, H_, 1, R_,
                nullptr, 0);
        }
        // merged0[b,n,h] = sum_r w[b,r]*msg[b,r,n,h]
        merge_kernel<<<(int)(((long)B_ * N_ * H_) / 256), 256>>>(bufB, wbuf + l * B_ * R_, bufA);

        // merged = merged0 @ out_W[l] + out_b[l]
        {
            dim3 grid(H_ / 128, (B_ * N_) / 128, 1);
            sgemm_kernel<false, true, false><<<grid, 256>>>(
                bufA, outW + (long)l * H_ * H_, bufB, B_ * N_, H_, H_,
                0, 0, 0, 1, 1,
                outb + (long)l * H_, 0, 1, 1,
                nullptr, 0);
        }
        // hidden = LN(x + merged)
        ln_kernel<<<B_ * N_, 256>>>(x, bufB, ln1g + (long)l * H_, ln1b + (long)l * H_, hidden);

        // ff1 = relu(hidden @ W1 + b1)
        {
            dim3 grid(FF_ / 128, (B_ * N_) / 128, 1);
            sgemm_kernel<true, true, false><<<grid, 256>>>(
                hidden, fW1 + (long)l * H_ * FF_, bufA, B_ * N_, FF_, H_,
                0, 0, 0, 1, 1,
                fb1 + (long)l * FF_, 0, 1, 1,
                nullptr, 0);
        }
        // ff2 = ff1 @ W2 + b2
        {
            dim3 grid(H_ / 128, (B_ * N_) / 128, 1);
            sgemm_kernel<false, true, false><<<grid, 256>>>(
                bufA, fW2 + (long)l * FF_ * H_, bufB, B_ * N_, H_, FF_,
                0, 0, 0, 1, 1,
                fb2 + (long)l * H_, 0, 1, 1,
                nullptr, 0);
        }
        // x = LN(hidden + ff2) ; final layer writes straight to d_out
        float* dst = (l == L_ - 1) ? out : xbuf;
        ln_kernel<<<B_ * N_, 256>>>(hidden, bufB, ln2g + (long)l * H_, ln2b + (long)l * H_, dst);
    }

    stat_kernel<<<1, 32>>>(wbuf, out + (long)B_ * N_ * H_);
}